// round 3
// baseline (speedup 1.0000x reference)
#include <cuda_runtime.h>
#include <cstdint>

#define NB   16
#define NN   25200
#define NCLS 80
#define CAP  1024
#define MAXDET 300
#define CONF_T 0.25f
#define IOU_T  0.45f
#define MAXWH  4096.0f

// key = score_bits(32) | (0x7FFF - n)(15) | class(7)
// larger key == higher score; tie -> smaller n. class bits never affect order
// (a given n appears in exactly one class bucket).
__device__ __forceinline__ unsigned key_low(unsigned n, unsigned j) {
    return ((0x7FFFu - n) << 7) | j;
}
__device__ __forceinline__ unsigned key_n(unsigned long long k) {
    return 0x7FFFu - (((unsigned)k >> 7) & 0x7FFFu);
}
__device__ __forceinline__ unsigned key_cls(unsigned long long k) {
    return (unsigned)k & 0x7Fu;
}

// ---------------- scratch ----------------
__device__ int                g_bcnt[NB * NCLS];
__device__ unsigned long long g_bkeys[(size_t)NB * NCLS * CAP];
__device__ int                g_kcnt[NB * NCLS];
__device__ unsigned long long g_kkeys[(size_t)NB * NCLS * CAP];

__global__ void k_init() {
    int i = blockIdx.x * blockDim.x + threadIdx.x;
    if (i < NB * NCLS) { g_bcnt[i] = 0; g_kcnt[i] = 0; }
}

// ---------------- 1) decode: warp per row, coalesced ----------------
__global__ __launch_bounds__(256) void k_decode(const float* __restrict__ pred) {
    int warp = (blockIdx.x * blockDim.x + threadIdx.x) >> 5;
    int lane = threadIdx.x & 31;
    if (warp >= NB * NN) return;
    const float* p = pred + (size_t)warp * 85;
    float obj = __ldg(p + 4);                 // broadcast (same address all lanes)
    float best = -1.0f;
    int   bj = 127;
    #pragma unroll
    for (int s = 0; s < 3; s++) {
        int k = lane + 32 * s;
        if (k < NCLS) {
            float v = __ldg(p + 5 + k) * obj; // exact reference arithmetic
            if (v > best) { best = v; bj = k; }  // strict > keeps lowest k in-lane
        }
    }
    // warp argmax, tie -> lower class index (== reference first-max)
    #pragma unroll
    for (int o = 16; o > 0; o >>= 1) {
        float ov = __shfl_down_sync(0xffffffffu, best, o);
        int   oj = __shfl_down_sync(0xffffffffu, bj, o);
        if (ov > best || (ov == best && oj < bj)) { best = ov; bj = oj; }
    }
    if (lane == 0 && obj > CONF_T && best > CONF_T) {
        int b = warp / NN;
        unsigned n = (unsigned)(warp % NN);
        int bucket = b * NCLS + bj;
        int pos = atomicAdd(&g_bcnt[bucket], 1);
        if (pos < CAP) {
            g_bkeys[(size_t)bucket * CAP + pos] =
                ((unsigned long long)__float_as_uint(best) << 32) |
                (unsigned long long)key_low(n, (unsigned)bj);
        }
    }
}

// ---------------- 2) per-bucket sort + greedy NMS ----------------
__global__ __launch_bounds__(256) void k_nms(const float* __restrict__ pred) {
    __shared__ unsigned long long sk[CAP];
    __shared__ float sx0[CAP], sy0[CAP], sx1[CAP], sy1[CAP], sa[CAP];
    __shared__ unsigned char sup[CAP];

    int bucket = blockIdx.x;
    int b = bucket / NCLS;
    int c = bucket % NCLS;
    int tid = threadIdx.x;

    int cnt = g_bcnt[bucket];
    if (cnt > CAP) cnt = CAP;
    if (cnt == 0) { if (tid == 0) g_kcnt[bucket] = 0; return; }

    int m = 1;                     // next pow2 >= cnt
    while (m < cnt) m <<= 1;

    for (int t = tid; t < m; t += 256)
        sk[t] = (t < cnt) ? g_bkeys[(size_t)bucket * CAP + t] : 0ULL;
    __syncthreads();

    if (cnt > 1) {
        for (int k = 2; k <= m; k <<= 1) {
            for (int j = k >> 1; j > 0; j >>= 1) {
                for (int t = tid; t < m; t += 256) {
                    int p = t ^ j;
                    if (p > t) {
                        bool up = ((t & k) == 0);
                        unsigned long long a = sk[t], bb = sk[p];
                        if ((a < bb) == up) { sk[t] = bb; sk[p] = a; }
                    }
                }
                __syncthreads();
            }
        }
    }

    float off = (float)c * MAXWH;
    for (int t = tid; t < cnt; t += 256) {
        unsigned n = key_n(sk[t]);
        const float* p = pred + ((size_t)b * NN + n) * 85;
        float cx = p[0], cy = p[1], w = p[2], h = p[3];
        float x0 = cx - w * 0.5f, y0 = cy - h * 0.5f;
        float x1 = cx + w * 0.5f, y1 = cy + h * 0.5f;
        x0 += off; y0 += off; x1 += off; y1 += off;
        sx0[t] = x0; sy0[t] = y0; sx1[t] = x1; sy1[t] = y1;
        sa[t]  = (x1 - x0) * (y1 - y0);
        sup[t] = 0;
    }
    __syncthreads();

    int kept = 0;
    for (int i = 0; i < cnt; i++) {
        __syncthreads();
        if (sup[i]) continue;
        if (tid == 0)
            g_kkeys[(size_t)bucket * CAP + kept] = sk[i];
        kept++;
        float bx0 = sx0[i], by0 = sy0[i], bx1 = sx1[i], by1 = sy1[i], ba = sa[i];
        for (int t = i + 1 + tid; t < cnt; t += 256) {
            float ltx = fmaxf(bx0, sx0[t]);
            float lty = fmaxf(by0, sy0[t]);
            float rbx = fminf(bx1, sx1[t]);
            float rby = fminf(by1, sy1[t]);
            float iw = fmaxf(rbx - ltx, 0.0f);
            float ih = fmaxf(rby - lty, 0.0f);
            float inter = iw * ih;
            float iou = inter / (((ba + sa[t]) - inter) + 1e-9f);
            if (iou > IOU_T) sup[t] = 1;
        }
    }
    if (tid == 0) g_kcnt[bucket] = kept;
}

// ---------------- 3) top-300 via radix select + bitonic sort ----------------
__global__ __launch_bounds__(256) void k_merge(const float* __restrict__ pred,
                                               const float* __restrict__ logits,
                                               float* __restrict__ out) {
    int b = blockIdx.x;
    int tid = threadIdx.x;
    __shared__ int s_kc[NCLS];
    __shared__ int s_hist[256];
    __shared__ unsigned long long s_keys[512];
    __shared__ int s_cnt;
    __shared__ unsigned long long s_prefix;
    __shared__ int s_k;
    __shared__ int s_total;

    for (int c = tid; c < NCLS; c += 256) {
        int kc = g_kcnt[b * NCLS + c];
        s_kc[c] = (kc > MAXDET) ? MAXDET : kc;   // beyond 300/class can't reach top-300
    }
    __syncthreads();
    if (tid == 0) {
        int t = 0;
        for (int c = 0; c < NCLS; c++) t += s_kc[c];
        s_total = t;
        s_prefix = 0ULL;
        s_k = MAXDET;
        s_cnt = 0;
    }
    __syncthreads();
    int total = s_total;
    int tsel = (total < MAXDET) ? total : MAXDET;

    unsigned long long T;
    if (total > MAXDET) {
        // MSB radix select of the MAXDET-th largest 64-bit key
        for (int byte = 7; byte >= 0; byte--) {
            for (int i = tid; i < 256; i += 256) s_hist[i] = 0;
            __syncthreads();
            unsigned long long pref = s_prefix;
            unsigned long long mask = (byte == 7) ? 0ULL : (~0ULL << ((byte + 1) * 8));
            for (int idx = tid; idx < NCLS * MAXDET; idx += 256) {
                int c = idx / MAXDET, i = idx % MAXDET;
                if (i < s_kc[c]) {
                    unsigned long long key = g_kkeys[(size_t)(b * NCLS + c) * CAP + i];
                    if ((key & mask) == pref)
                        atomicAdd(&s_hist[(int)((key >> (byte * 8)) & 0xFF)], 1);
                }
            }
            __syncthreads();
            if (tid == 0) {
                int k = s_k, bin = 0;
                for (int v = 255; v >= 0; v--) {
                    int h = s_hist[v];
                    if (h >= k) { bin = v; break; }
                    k -= h;
                }
                s_k = k;
                s_prefix = pref | ((unsigned long long)bin << (byte * 8));
            }
            __syncthreads();
        }
        T = s_prefix;          // exact 300th-largest key (keys are unique)
    } else {
        T = 1ULL;              // all keys (keys are always > 0)
    }

    for (int i = tid; i < 512; i += 256) s_keys[i] = 0ULL;
    __syncthreads();
    for (int idx = tid; idx < NCLS * MAXDET; idx += 256) {
        int c = idx / MAXDET, i = idx % MAXDET;
        if (i < s_kc[c]) {
            unsigned long long key = g_kkeys[(size_t)(b * NCLS + c) * CAP + i];
            if (key >= T) {
                int pos = atomicAdd(&s_cnt, 1);
                if (pos < 512) s_keys[pos] = key;
            }
        }
    }
    __syncthreads();

    // bitonic sort 512 descending
    for (int k = 2; k <= 512; k <<= 1) {
        for (int j = k >> 1; j > 0; j >>= 1) {
            for (int t = tid; t < 512; t += 256) {
                int p = t ^ j;
                if (p > t) {
                    bool up = ((t & k) == 0);
                    unsigned long long a = s_keys[t], bb = s_keys[p];
                    if ((a < bb) == up) { s_keys[t] = bb; s_keys[p] = a; }
                }
            }
            __syncthreads();
        }
    }

    float* dets  = out;                               // [16,300,6]
    float* lg    = out + (size_t)NB * MAXDET * 6;     // [16,300,80]
    float* keepo = out + (size_t)NB * MAXDET * 86;    // [16,300]

    for (int r = tid; r < MAXDET; r += 256) {
        float d0 = 0, d1 = 0, d2 = 0, d3 = 0, d4 = 0, d5 = 0, kf = 0;
        if (r < tsel) {
            unsigned long long key = s_keys[r];
            unsigned n = key_n(key);
            float conf = __uint_as_float((unsigned)(key >> 32));
            const float* p = pred + ((size_t)b * NN + n) * 85;
            float cx = p[0], cy = p[1], w = p[2], h = p[3];
            d0 = cx - w * 0.5f; d1 = cy - h * 0.5f;
            d2 = cx + w * 0.5f; d3 = cy + h * 0.5f;
            d4 = conf; d5 = (float)key_cls(key); kf = 1.0f;
        }
        float* dr = dets + ((size_t)b * MAXDET + r) * 6;
        dr[0] = d0; dr[1] = d1; dr[2] = d2; dr[3] = d3; dr[4] = d4; dr[5] = d5;
        keepo[(size_t)b * MAXDET + r] = kf;
    }
    for (int idx = tid; idx < MAXDET * NCLS; idx += 256) {
        int r = idx / NCLS, col = idx % NCLS;
        float v = 0.0f;
        if (r < tsel)
            v = logits[((size_t)b * NN + key_n(s_keys[r])) * NCLS + col];
        lg[((size_t)b * MAXDET + r) * NCLS + col] = v;
    }
}

extern "C" void kernel_launch(void* const* d_in, const int* in_sizes, int n_in,
                              void* d_out, int out_size) {
    const float* pred;
    const float* logits;
    if (in_sizes[0] == NB * NN * 85) {
        pred = (const float*)d_in[0];
        logits = (const float*)d_in[1];
    } else {
        pred = (const float*)d_in[1];
        logits = (const float*)d_in[0];
    }
    float* out = (float*)d_out;

    k_init<<<(NB * NCLS + 255) / 256, 256>>>();
    k_decode<<<(NB * NN * 32 + 255) / 256, 256>>>(pred);
    k_nms<<<NB * NCLS, 256>>>(pred);
    k_merge<<<NB, 256>>>(pred, logits, out);
}

// round 6
// speedup vs baseline: 2.4203x; 2.4203x over previous
#include <cuda_runtime.h>
#include <cstdint>

#define NB     16
#define NN     25200
#define NCLS   80
#define MAXDET 300
#define CONF_T 0.25f
#define IOU_T  0.45f
#define MAXWH  4096.0f

#define HBINS   4096          // histogram bins over score bits
#define HBASE   0x3E800000u   // float bits of 0.25
#define HSHIFT  13
#define SELECT_MIN 600        // want >=600 candidates above threshold
#define CAPI   32768          // per-image candidate list capacity
#define CAPB   128            // per-(image,class) bucket capacity (above T0)
#define ROWS_PB 80            // rows per decode block (divides NN: 25200/80=315)

// key = score_bits(32) | (0x7FFF - n)(15) | class(7)
// larger key == higher score; tie -> smaller n (matches argmax first-occurrence).
__device__ __forceinline__ unsigned key_low(unsigned n, unsigned j) {
    return ((0x7FFFu - n) << 7) | j;
}
__device__ __forceinline__ unsigned key_n(unsigned long long k) {
    return 0x7FFFu - (((unsigned)k >> 7) & 0x7FFFu);
}
__device__ __forceinline__ unsigned key_cls(unsigned long long k) {
    return (unsigned)k & 0x7Fu;
}

// ---------------- scratch ----------------
__device__ int                g_hist[NB * HBINS];
__device__ int                g_icnt[NB];
__device__ unsigned long long g_cand[(size_t)NB * CAPI];
__device__ unsigned           g_T0bits[NB];
__device__ int                g_bcnt[NB * NCLS];
__device__ unsigned long long g_bkeys[(size_t)NB * NCLS * CAPB];
__device__ int                g_kcnt[NB * NCLS];
__device__ unsigned long long g_kkeys[(size_t)NB * NCLS * CAPB];

__global__ void k_init() {
    int i = blockIdx.x * blockDim.x + threadIdx.x;
    if (i < NB * HBINS) g_hist[i] = 0;
    if (i < NB) g_icnt[i] = 0;
    if (i < NB * NCLS) { g_bcnt[i] = 0; g_kcnt[i] = 0; }
}

// ---------------- 1) decode: staged float4 load, warp per row ----------------
__global__ __launch_bounds__(256) void k_decode(const float* __restrict__ pred) {
    __shared__ float s[ROWS_PB * 85];     // 27200 B
    int tid = threadIdx.x;

    const float4* src = (const float4*)(pred + (size_t)blockIdx.x * ROWS_PB * 85);
    float4* dst = (float4*)s;
    #pragma unroll
    for (int i = tid; i < ROWS_PB * 85 / 4; i += 256) dst[i] = src[i];
    __syncthreads();

    int w = tid >> 5, lane = tid & 31;
    int b = blockIdx.x / (NN / ROWS_PB);
    int n0 = (blockIdx.x % (NN / ROWS_PB)) * ROWS_PB + w * (ROWS_PB / 8);

    unsigned long long buf[ROWS_PB / 8];
    int nb = 0;
    #pragma unroll
    for (int r = 0; r < ROWS_PB / 8; r++) {
        int lr = w * (ROWS_PB / 8) + r;
        float obj = s[lr * 85 + 4];
        float best = -1.0f; int bj = 127;
        #pragma unroll
        for (int t = 0; t < 3; t++) {
            int k = lane + 32 * t;
            if (k < NCLS) {
                float v = s[lr * 85 + 5 + k] * obj;   // exact reference arithmetic
                if (v > best) { best = v; bj = k; }   // strict > -> lowest k in lane
            }
        }
        #pragma unroll
        for (int o = 16; o > 0; o >>= 1) {
            float ov = __shfl_down_sync(0xffffffffu, best, o);
            int   oj = __shfl_down_sync(0xffffffffu, bj, o);
            if (ov > best || (ov == best && oj < bj)) { best = ov; bj = oj; }
        }
        if (lane == 0 && obj > CONF_T && best > CONF_T) {
            unsigned bits = __float_as_uint(best);
            int bin = (int)((bits - HBASE) >> HSHIFT);
            if (bin < 0) bin = 0;
            if (bin > HBINS - 1) bin = HBINS - 1;
            atomicAdd(&g_hist[b * HBINS + bin], 1);
            buf[nb++] = ((unsigned long long)bits << 32) |
                        (unsigned long long)key_low((unsigned)(n0 + r), (unsigned)bj);
        }
    }
    if (lane == 0 && nb) {
        int base = atomicAdd(&g_icnt[b], nb);
        for (int i = 0; i < nb; i++) {
            int p = base + i;
            if (p < CAPI) g_cand[(size_t)b * CAPI + p] = buf[i];
        }
    }
}

// ---------------- 2) per-image score threshold from histogram ----------------
__global__ __launch_bounds__(512) void k_thresh() {
    int wimg = threadIdx.x >> 5, lane = threadIdx.x & 31;
    if (wimg >= NB) return;
    int run = 0;
    bool done = false;
    for (int chunk = HBINS / 32 - 1; chunk >= 0 && !done; chunk--) {
        int bin = chunk * 32 + (31 - lane);          // lane0 = highest bin
        int v = g_hist[wimg * HBINS + bin];
        int pref = v;
        #pragma unroll
        for (int o = 1; o < 32; o <<= 1) {
            int u = __shfl_up_sync(0xffffffffu, pref, o);
            if (lane >= o) pref += u;
        }
        int tot = __shfl_sync(0xffffffffu, pref, 31);
        unsigned m = __ballot_sync(0xffffffffu, run + pref >= SELECT_MIN);
        if (m) {
            int fl = __ffs(m) - 1;                   // first lane = highest bin crossing
            int B = __shfl_sync(0xffffffffu, bin, fl);
            if (lane == 0) g_T0bits[wimg] = HBASE + ((unsigned)B << HSHIFT);
            done = true;
        } else {
            run += tot;
            if (chunk == 0 && lane == 0) g_T0bits[wimg] = HBASE;  // take everything
        }
    }
}

// ---------------- 3) bucket candidates above threshold by class ----------------
__global__ __launch_bounds__(256) void k_bucket() {
    int b = blockIdx.x >> 3;
    int part = blockIdx.x & 7;
    int cnt = g_icnt[b]; if (cnt > CAPI) cnt = CAPI;
    unsigned long long T = ((unsigned long long)g_T0bits[b]) << 32;
    for (int i = part * 256 + threadIdx.x; i < cnt; i += 8 * 256) {
        unsigned long long key = g_cand[(size_t)b * CAPI + i];
        if (key >= T) {
            int c = (int)key_cls(key);
            int pos = atomicAdd(&g_bcnt[b * NCLS + c], 1);
            if (pos < CAPB) g_bkeys[(size_t)(b * NCLS + c) * CAPB + pos] = key;
        }
    }
}

// ---------------- 4) warp-per-class sort + greedy NMS (registers, no barriers) -
__global__ __launch_bounds__(256) void k_nms(const float* __restrict__ pred) {
    __shared__ unsigned long long sk[8][CAPB];
    int w = threadIdx.x >> 5, lane = threadIdx.x & 31;
    int bucket = blockIdx.x * 8 + w;
    int b = bucket / NCLS, c = bucket % NCLS;

    int cnt = g_bcnt[bucket]; if (cnt > CAPB) cnt = CAPB;
    if (cnt == 0) { if (lane == 0) g_kcnt[bucket] = 0; return; }

    for (int t = lane; t < CAPB; t += 32)
        sk[w][t] = (t < cnt) ? g_bkeys[(size_t)bucket * CAPB + t] : 0ULL;
    __syncwarp();

    int m = 1; while (m < cnt) m <<= 1;
    if (cnt > 1) {
        for (int k = 2; k <= m; k <<= 1) {
            for (int j = k >> 1; j > 0; j >>= 1) {
                for (int t = lane; t < m; t += 32) {
                    int p = t ^ j;
                    if (p > t) {
                        bool up = ((t & k) == 0);
                        unsigned long long a = sk[w][t], bb = sk[w][p];
                        if ((a < bb) == up) { sk[w][t] = bb; sk[w][p] = a; }
                    }
                }
                __syncwarp();
            }
        }
    }

    // boxes in registers: slot s holds element lane + 32*s
    float x0[4], y0[4], x1[4], y1[4], ar[4];
    unsigned supm = 0;
    float off = (float)c * MAXWH;
    #pragma unroll
    for (int s = 0; s < 4; s++) {
        int t = lane + 32 * s;
        if (t < cnt) {
            unsigned n = key_n(sk[w][t]);
            const float* p = pred + ((size_t)b * NN + n) * 85;
            float cx = p[0], cy = p[1], wd = p[2], ht = p[3];
            float a0 = cx - wd * 0.5f, b0 = cy - ht * 0.5f;
            float a1 = cx + wd * 0.5f, b1 = cy + ht * 0.5f;
            a0 += off; b0 += off; a1 += off; b1 += off;
            x0[s] = a0; y0[s] = b0; x1[s] = a1; y1[s] = b1;
            ar[s] = (a1 - a0) * (b1 - b0);
        } else {
            supm |= 1u << s;
            x0[s] = 0; y0[s] = 0; x1[s] = 0; y1[s] = 0; ar[s] = 0;
        }
    }

    for (int i = 0; i < cnt; i++) {
        int src = i & 31, sl = i >> 5;      // sl uniform across warp
        float vx0 = (sl == 0) ? x0[0] : (sl == 1) ? x0[1] : (sl == 2) ? x0[2] : x0[3];
        float vy0 = (sl == 0) ? y0[0] : (sl == 1) ? y0[1] : (sl == 2) ? y0[2] : y0[3];
        float vx1 = (sl == 0) ? x1[0] : (sl == 1) ? x1[1] : (sl == 2) ? x1[2] : x1[3];
        float vy1 = (sl == 0) ? y1[0] : (sl == 1) ? y1[1] : (sl == 2) ? y1[2] : y1[3];
        float var = (sl == 0) ? ar[0] : (sl == 1) ? ar[1] : (sl == 2) ? ar[2] : ar[3];
        unsigned ps = __shfl_sync(0xffffffffu, supm, src);
        float bx0 = __shfl_sync(0xffffffffu, vx0, src);
        float by0 = __shfl_sync(0xffffffffu, vy0, src);
        float bx1 = __shfl_sync(0xffffffffu, vx1, src);
        float by1 = __shfl_sync(0xffffffffu, vy1, src);
        float ba  = __shfl_sync(0xffffffffu, var, src);
        if ((ps >> sl) & 1) continue;        // pivot suppressed: uniform
        #pragma unroll
        for (int s = 0; s < 4; s++) {
            int t = lane + 32 * s;
            if (t > i && !((supm >> s) & 1)) {
                float ltx = fmaxf(bx0, x0[s]);
                float lty = fmaxf(by0, y0[s]);
                float rbx = fminf(bx1, x1[s]);
                float rby = fminf(by1, y1[s]);
                float iw = fmaxf(rbx - ltx, 0.0f);
                float ih = fmaxf(rby - lty, 0.0f);
                float inter = iw * ih;
                float iou = inter / (((ba + ar[s]) - inter) + 1e-9f);
                if (iou > IOU_T) supm |= 1u << s;
            }
        }
    }

    // write kept keys in sorted (descending) order
    int base = 0;
    #pragma unroll
    for (int s = 0; s < 4; s++) {
        int t = lane + 32 * s;
        bool kp = (t < cnt) && !((supm >> s) & 1);
        unsigned mask = __ballot_sync(0xffffffffu, kp);
        if (kp) {
            int pos = base + __popc(mask & ((1u << lane) - 1));
            g_kkeys[(size_t)bucket * CAPB + pos] = sk[w][t];
        }
        base += __popc(mask);
    }
    if (lane == 0) g_kcnt[bucket] = base;
}

// ---------------- 5) per-image: gather kept, bitonic sort 1024, write out ------
__global__ __launch_bounds__(256) void k_merge(const float* __restrict__ pred,
                                               const float* __restrict__ logits,
                                               float* __restrict__ out) {
    int b = blockIdx.x;
    int tid = threadIdx.x;
    __shared__ unsigned long long sk[1024];
    __shared__ int s_off[NCLS + 1];

    for (int i = tid; i < 1024; i += 256) sk[i] = 0ULL;
    if (tid == 0) {
        int acc = 0;
        for (int c = 0; c < NCLS; c++) {
            s_off[c] = acc;
            int v = g_kcnt[b * NCLS + c];
            if (v > CAPB) v = CAPB;
            if (acc + v > 1024) v = 1024 - acc;
            acc += v;
        }
        s_off[NCLS] = acc;
    }
    __syncthreads();
    int total = s_off[NCLS];

    for (int c = 0; c < NCLS; c++) {
        int off = s_off[c], len = s_off[c + 1] - off;
        for (int t = tid; t < len; t += 256)
            sk[off + t] = g_kkeys[(size_t)(b * NCLS + c) * CAPB + t];
    }
    __syncthreads();

    // bitonic sort 1024 descending (zeros sink)
    for (int k = 2; k <= 1024; k <<= 1) {
        for (int j = k >> 1; j > 0; j >>= 1) {
            for (int t = tid; t < 1024; t += 256) {
                int p = t ^ j;
                if (p > t) {
                    bool up = ((t & k) == 0);
                    unsigned long long a = sk[t], bb = sk[p];
                    if ((a < bb) == up) { sk[t] = bb; sk[p] = a; }
                }
            }
            __syncthreads();
        }
    }

    int tsel = (total < MAXDET) ? total : MAXDET;

    float* dets  = out;                               // [16,300,6]
    float* lg    = out + (size_t)NB * MAXDET * 6;     // [16,300,80]
    float* keepo = out + (size_t)NB * MAXDET * 86;    // [16,300]

    for (int r = tid; r < MAXDET; r += 256) {
        float d0 = 0, d1 = 0, d2 = 0, d3 = 0, d4 = 0, d5 = 0, kf = 0;
        if (r < tsel) {
            unsigned long long key = sk[r];
            unsigned n = key_n(key);
            float conf = __uint_as_float((unsigned)(key >> 32));
            const float* p = pred + ((size_t)b * NN + n) * 85;
            float cx = p[0], cy = p[1], wd = p[2], ht = p[3];
            d0 = cx - wd * 0.5f; d1 = cy - ht * 0.5f;
            d2 = cx + wd * 0.5f; d3 = cy + ht * 0.5f;
            d4 = conf; d5 = (float)key_cls(key); kf = 1.0f;
        }
        float* dr = dets + ((size_t)b * MAXDET + r) * 6;
        dr[0] = d0; dr[1] = d1; dr[2] = d2; dr[3] = d3; dr[4] = d4; dr[5] = d5;
        keepo[(size_t)b * MAXDET + r] = kf;
    }
    for (int idx = tid; idx < MAXDET * NCLS; idx += 256) {
        int r = idx / NCLS, col = idx % NCLS;
        float v = 0.0f;
        if (r < tsel)
            v = logits[((size_t)b * NN + key_n(sk[r])) * NCLS + col];
        lg[((size_t)b * MAXDET + r) * NCLS + col] = v;
    }
}

extern "C" void kernel_launch(void* const* d_in, const int* in_sizes, int n_in,
                              void* d_out, int out_size) {
    const float* pred;
    const float* logits;
    if (in_sizes[0] == NB * NN * 85) {
        pred = (const float*)d_in[0];
        logits = (const float*)d_in[1];
    } else {
        pred = (const float*)d_in[1];
        logits = (const float*)d_in[0];
    }
    float* out = (float*)d_out;

    k_init<<<(NB * HBINS + 255) / 256, 256>>>();
    k_decode<<<NB * (NN / ROWS_PB), 256>>>(pred);
    k_thresh<<<1, 512>>>();
    k_bucket<<<NB * 8, 256>>>();
    k_nms<<<NB * NCLS / 8, 256>>>(pred);
    k_merge<<<NB, 256>>>(pred, logits, out);
}

// round 11
// speedup vs baseline: 3.0038x; 1.2411x over previous
#include <cuda_runtime.h>
#include <cstdint>

#define NB     16
#define NN     25200
#define NCLS   80
#define MAXDET 300
#define CONF_T 0.25f
#define IOU_T  0.45f
#define MAXWH  4096.0f

#define HBINS   4096          // histogram bins over score bits
#define HBASE   0x3E800000u   // float bits of 0.25
#define HSHIFT  13
#define SELECT_MIN 600        // want >=600 candidates above threshold
#define CAPI   32768          // per-image candidate list capacity
#define CAPC   64             // per-(image,class) smem bucket capacity
#define ROWS_PB 80            // rows per decode block (25200/80=315)

typedef unsigned long long u64;

// key = score_bits(32) | (0x7FFF - n)(15) | class(7)
__device__ __forceinline__ unsigned key_low(unsigned n, unsigned j) {
    return ((0x7FFFu - n) << 7) | j;
}
__device__ __forceinline__ unsigned key_n(u64 k) {
    return 0x7FFFu - (((unsigned)k >> 7) & 0x7FFFu);
}
__device__ __forceinline__ unsigned key_cls(u64 k) {
    return (unsigned)k & 0x7Fu;
}

// ---------------- scratch ----------------
__device__ int g_hist[NB * HBINS];
__device__ int g_icnt[NB];
__device__ u64 g_cand[(size_t)NB * CAPI];

__global__ void k_init() {
    int i = blockIdx.x * blockDim.x + threadIdx.x;
    if (i < NB * HBINS) g_hist[i] = 0;
    if (i < NB) g_icnt[i] = 0;
}

// ---------------- 1) decode: staged float4 load, warp per row ----------------
__global__ __launch_bounds__(256) void k_decode(const float* __restrict__ pred) {
    __shared__ float s[ROWS_PB * 85];
    int tid = threadIdx.x;

    const float4* src = (const float4*)(pred + (size_t)blockIdx.x * ROWS_PB * 85);
    float4* dst = (float4*)s;
    #pragma unroll
    for (int i = tid; i < ROWS_PB * 85 / 4; i += 256) dst[i] = src[i];
    __syncthreads();

    int w = tid >> 5, lane = tid & 31;
    int b = blockIdx.x / (NN / ROWS_PB);
    int n0 = (blockIdx.x % (NN / ROWS_PB)) * ROWS_PB + w * (ROWS_PB / 8);

    u64 buf[ROWS_PB / 8];
    int nb = 0;
    #pragma unroll
    for (int r = 0; r < ROWS_PB / 8; r++) {
        int lr = w * (ROWS_PB / 8) + r;
        float obj = s[lr * 85 + 4];
        float best = -1.0f; int bj = 127;
        #pragma unroll
        for (int t = 0; t < 3; t++) {
            int k = lane + 32 * t;
            if (k < NCLS) {
                float v = s[lr * 85 + 5 + k] * obj;   // exact reference arithmetic
                if (v > best) { best = v; bj = k; }
            }
        }
        #pragma unroll
        for (int o = 16; o > 0; o >>= 1) {
            float ov = __shfl_down_sync(0xffffffffu, best, o);
            int   oj = __shfl_down_sync(0xffffffffu, bj, o);
            if (ov > best || (ov == best && oj < bj)) { best = ov; bj = oj; }
        }
        if (lane == 0 && obj > CONF_T && best > CONF_T) {
            unsigned bits = __float_as_uint(best);
            int bin = (int)((bits - HBASE) >> HSHIFT);
            if (bin < 0) bin = 0;
            if (bin > HBINS - 1) bin = HBINS - 1;
            atomicAdd(&g_hist[b * HBINS + bin], 1);
            buf[nb++] = ((u64)bits << 32) |
                        (u64)key_low((unsigned)(n0 + r), (unsigned)bj);
        }
    }
    if (lane == 0 && nb) {
        int base = atomicAdd(&g_icnt[b], nb);
        for (int i = 0; i < nb; i++) {
            int p = base + i;
            if (p < CAPI) g_cand[(size_t)b * CAPI + p] = buf[i];
        }
    }
}

// ---------------- 2) fused per-image: threshold + bucket + NMS + sort + out ----
#define SMEM_POST ((NCLS * CAPC + 1024) * 8 + (NCLS + 256 + 8) * 4)

__global__ __launch_bounds__(256) void k_post(const float* __restrict__ pred,
                                              const float* __restrict__ logits,
                                              float* __restrict__ out) {
    extern __shared__ unsigned char dsm[];
    u64* s_cls  = (u64*)dsm;                      // [NCLS*CAPC]
    u64* s_sort = s_cls + NCLS * CAPC;            // [1024]
    int* s_ccnt = (int*)(s_sort + 1024);          // [NCLS]
    int* s_part = s_ccnt + NCLS;                  // [256]
    int* s_misc = s_part + 256;                   // [0]=T0bits [1]=kept count

    int b = blockIdx.x;
    int tid = threadIdx.x;
    int w = tid >> 5, lane = tid & 31;

    // init smem
    for (int i = tid; i < NCLS * CAPC; i += 256) s_cls[i] = 0ULL;
    for (int i = tid; i < 1024; i += 256) s_sort[i] = 0ULL;
    for (int i = tid; i < NCLS; i += 256) s_ccnt[i] = 0;
    if (tid == 0) s_misc[1] = 0;

    // ---- threshold: suffix scan of 4096-bin histogram ----
    {
        int sum = 0;
        #pragma unroll
        for (int i = 0; i < 16; i++) sum += g_hist[b * HBINS + tid * 16 + i];
        s_part[tid] = sum;
        __syncthreads();
        for (int off = 1; off < 256; off <<= 1) {
            int add = (tid + off < 256) ? s_part[tid + off] : 0;
            __syncthreads();
            s_part[tid] += add;
            __syncthreads();
        }
        if (tid == 0) {
            unsigned bits;
            if (s_part[0] < SELECT_MIN) {
                bits = HBASE;                      // take everything
            } else {
                int ct = 255;
                while (s_part[ct] < SELECT_MIN) ct--;
                int cum = (ct < 255) ? s_part[ct + 1] : 0;
                int B = ct * 16;
                for (int bin = ct * 16 + 15; bin >= ct * 16; bin--) {
                    cum += g_hist[b * HBINS + bin];
                    if (cum >= SELECT_MIN) { B = bin; break; }
                }
                bits = HBASE + ((unsigned)B << HSHIFT);
            }
            s_misc[0] = (int)bits;
        }
    }
    __syncthreads();
    u64 T = ((u64)(unsigned)s_misc[0]) << 32;

    // ---- filter candidates above T into per-class smem lists ----
    {
        int cnt = g_icnt[b]; if (cnt > CAPI) cnt = CAPI;
        for (int i = tid; i < cnt; i += 256) {
            u64 key = g_cand[(size_t)b * CAPI + i];
            if (key >= T) {
                int c = (int)key_cls(key);
                int pos = atomicAdd(&s_ccnt[c], 1);
                if (pos < CAPC) s_cls[c * CAPC + pos] = key;
            }
        }
    }
    __syncthreads();

    // ---- warp-per-class: sort + greedy NMS + compact kept into s_sort ----
    for (int k10 = 0; k10 < NCLS / 8; k10++) {
        int c = w + 8 * k10;
        int cntc = s_ccnt[c]; if (cntc > CAPC) cntc = CAPC;
        if (cntc == 0) continue;
        u64* L = s_cls + c * CAPC;

        if (cntc > 1) {
            int m = 1; while (m < cntc) m <<= 1;
            for (int k = 2; k <= m; k <<= 1) {
                for (int j = k >> 1; j > 0; j >>= 1) {
                    for (int t = lane; t < m; t += 32) {
                        int p = t ^ j;
                        if (p > t) {
                            bool up = ((t & k) == 0);
                            u64 a = L[t], bb = L[p];
                            if ((a < bb) == up) { L[t] = bb; L[p] = a; }
                        }
                    }
                    __syncwarp();
                }
            }
        }

        // boxes in registers: slot s holds element lane + 32*s (cntc <= 64)
        float x0[2], y0[2], x1[2], y1[2], ar[2];
        unsigned supm = 0;
        float off = (float)c * MAXWH;
        #pragma unroll
        for (int s = 0; s < 2; s++) {
            int t = lane + 32 * s;
            if (t < cntc) {
                unsigned n = key_n(L[t]);
                const float* p = pred + ((size_t)b * NN + n) * 85;
                float cx = p[0], cy = p[1], wd = p[2], ht = p[3];
                float a0 = cx - wd * 0.5f, b0 = cy - ht * 0.5f;
                float a1 = cx + wd * 0.5f, b1 = cy + ht * 0.5f;
                a0 += off; b0 += off; a1 += off; b1 += off;
                x0[s] = a0; y0[s] = b0; x1[s] = a1; y1[s] = b1;
                ar[s] = (a1 - a0) * (b1 - b0);
            } else {
                supm |= 1u << s;
                x0[s] = 0; y0[s] = 0; x1[s] = 0; y1[s] = 0; ar[s] = 0;
            }
        }

        for (int i = 0; i < cntc; i++) {
            int src = i & 31, sl = i >> 5;
            float vx0 = sl ? x0[1] : x0[0];
            float vy0 = sl ? y0[1] : y0[0];
            float vx1 = sl ? x1[1] : x1[0];
            float vy1 = sl ? y1[1] : y1[0];
            float var = sl ? ar[1] : ar[0];
            unsigned ps = __shfl_sync(0xffffffffu, supm, src);
            float bx0 = __shfl_sync(0xffffffffu, vx0, src);
            float by0 = __shfl_sync(0xffffffffu, vy0, src);
            float bx1 = __shfl_sync(0xffffffffu, vx1, src);
            float by1 = __shfl_sync(0xffffffffu, vy1, src);
            float ba  = __shfl_sync(0xffffffffu, var, src);
            if ((ps >> sl) & 1) continue;     // pivot suppressed: uniform branch
            #pragma unroll
            for (int s = 0; s < 2; s++) {
                int t = lane + 32 * s;
                if (t > i && !((supm >> s) & 1)) {
                    float ltx = fmaxf(bx0, x0[s]);
                    float lty = fmaxf(by0, y0[s]);
                    float rbx = fminf(bx1, x1[s]);
                    float rby = fminf(by1, y1[s]);
                    float iw = fmaxf(rbx - ltx, 0.0f);
                    float ih = fmaxf(rby - lty, 0.0f);
                    float inter = iw * ih;
                    float iou = inter / (((ba + ar[s]) - inter) + 1e-9f);
                    if (iou > IOU_T) supm |= 1u << s;
                }
            }
        }

        // compact kept keys into s_sort (order irrelevant, re-sorted below)
        #pragma unroll
        for (int s = 0; s < 2; s++) {
            int t = lane + 32 * s;
            bool kp = (t < cntc) && !((supm >> s) & 1);
            unsigned mask = __ballot_sync(0xffffffffu, kp);
            if (mask) {
                int leader = __ffs(mask) - 1;
                int base = 0;
                if (lane == leader) base = atomicAdd(&s_misc[1], __popc(mask));
                base = __shfl_sync(0xffffffffu, base, leader);
                if (kp) {
                    int pos = base + __popc(mask & ((1u << lane) - 1));
                    if (pos < 1024) s_sort[pos] = L[t];
                }
            }
        }
    }
    __syncthreads();
    int kept = s_misc[1]; if (kept > 1024) kept = 1024;

    // ---- bitonic sort 1024 descending (zeros sink) ----
    for (int k = 2; k <= 1024; k <<= 1) {
        for (int j = k >> 1; j > 0; j >>= 1) {
            for (int t = tid; t < 1024; t += 256) {
                int p = t ^ j;
                if (p > t) {
                    bool up = ((t & k) == 0);
                    u64 a = s_sort[t], bb = s_sort[p];
                    if ((a < bb) == up) { s_sort[t] = bb; s_sort[p] = a; }
                }
            }
            __syncthreads();
        }
    }

    int tsel = (kept < MAXDET) ? kept : MAXDET;

    float* dets  = out;                               // [16,300,6]
    float* lg    = out + (size_t)NB * MAXDET * 6;     // [16,300,80]
    float* keepo = out + (size_t)NB * MAXDET * 86;    // [16,300]

    for (int r = tid; r < MAXDET; r += 256) {
        float d0 = 0, d1 = 0, d2 = 0, d3 = 0, d4 = 0, d5 = 0, kf = 0;
        if (r < tsel) {
            u64 key = s_sort[r];
            unsigned n = key_n(key);
            float conf = __uint_as_float((unsigned)(key >> 32));
            const float* p = pred + ((size_t)b * NN + n) * 85;
            float cx = p[0], cy = p[1], wd = p[2], ht = p[3];
            d0 = cx - wd * 0.5f; d1 = cy - ht * 0.5f;
            d2 = cx + wd * 0.5f; d3 = cy + ht * 0.5f;
            d4 = conf; d5 = (float)key_cls(key); kf = 1.0f;
        }
        float* dr = dets + ((size_t)b * MAXDET + r) * 6;
        dr[0] = d0; dr[1] = d1; dr[2] = d2; dr[3] = d3; dr[4] = d4; dr[5] = d5;
        keepo[(size_t)b * MAXDET + r] = kf;
    }
    for (int idx = tid; idx < MAXDET * NCLS; idx += 256) {
        int r = idx / NCLS, col = idx % NCLS;
        float v = 0.0f;
        if (r < tsel)
            v = logits[((size_t)b * NN + key_n(s_sort[r])) * NCLS + col];
        lg[((size_t)b * MAXDET + r) * NCLS + col] = v;
    }
}

extern "C" void kernel_launch(void* const* d_in, const int* in_sizes, int n_in,
                              void* d_out, int out_size) {
    const float* pred;
    const float* logits;
    if (in_sizes[0] == NB * NN * 85) {
        pred = (const float*)d_in[0];
        logits = (const float*)d_in[1];
    } else {
        pred = (const float*)d_in[1];
        logits = (const float*)d_in[0];
    }
    float* out = (float*)d_out;

    cudaFuncSetAttribute(k_post, cudaFuncAttributeMaxDynamicSharedMemorySize,
                         SMEM_POST);

    k_init<<<(NB * HBINS + 255) / 256, 256>>>();
    k_decode<<<NB * (NN / ROWS_PB), 256>>>(pred);
    k_post<<<NB, 256, SMEM_POST>>>(pred, logits, out);
}

// round 13
// speedup vs baseline: 3.3629x; 1.1195x over previous
#include <cuda_runtime.h>
#include <cstdint>

#define NB     16
#define NN     25200
#define NCLS   80
#define MAXDET 300
#define CONF_T 0.25f
#define IOU_T  0.45f
#define MAXWH  4096.0f

#define HBINS   4096          // histogram bins over score bits
#define HBASE   0x3E800000u   // float bits of 0.25
#define HSHIFT  13
#define SELECT_MIN 600        // want >=600 candidates above threshold
#define CAPI   32768          // per-image candidate list capacity
#define CAPC   64             // per-(image,class) smem bucket capacity
#define RPB    112            // rows per decode block (25200/112 = 225)
#define STR    92             // smem floats per row (92/4=23 f4, odd -> no conflicts)

typedef unsigned long long u64;

// key = score_bits(32) | (0x7FFF - n)(15) | class(7)
__device__ __forceinline__ unsigned key_low(unsigned n, unsigned j) {
    return ((0x7FFFu - n) << 7) | j;
}
__device__ __forceinline__ unsigned key_n(u64 k) {
    return 0x7FFFu - (((unsigned)k >> 7) & 0x7FFFu);
}
__device__ __forceinline__ unsigned key_cls(u64 k) {
    return (unsigned)k & 0x7Fu;
}

// ---------------- scratch ----------------
__device__ int g_icnt[NB];
__device__ u64 g_cand[(size_t)NB * CAPI];

__global__ void k_init() {
    if (threadIdx.x < NB) g_icnt[threadIdx.x] = 0;
}

// ---------------- 1) decode: staged smem, half-row per thread ----------------
__global__ __launch_bounds__(256) void k_decode(const float* __restrict__ pred) {
    __shared__ float s[RPB * STR];                 // 41216 B
    int tid = threadIdx.x;

    // stage RPB rows (85 floats each) -> smem at stride STR
    const float4* g = (const float4*)(pred + (size_t)blockIdx.x * RPB * 85);
    #pragma unroll 4
    for (int i = tid; i < RPB * 85 / 4; i += 256) {
        float4 v = g[i];
        int f = 4 * i;
        int r = f / 85, c = f - r * 85;
        // scatter 4 elements; a chunk may cross a row boundary
        float vv[4] = {v.x, v.y, v.z, v.w};
        #pragma unroll
        for (int e = 0; e < 4; e++) {
            int ce = c + e;
            if (ce < 85) s[r * STR + ce] = vv[e];
            else         s[(r + 1) * STR + (ce - 85)] = vv[e];
        }
    }
    __syncthreads();

    if (tid >= 2 * RPB) return;                    // warps 0..6 fully active
    int row = tid >> 1, half = tid & 1;
    int lane = tid & 31;
    const float4* rs = (const float4*)s + row * 23;

    float obj, best = -1.0f;
    int bj = 127;
    if (half == 0) {
        // chunk 1: floats 4..7 = obj, c0,c1,c2 ; chunks 2..11: c = 4j-5..4j-2
        float4 v = rs[1];
        obj = v.x;
        { float t = v.y * obj; if (t > best) { best = t; bj = 0; } }
        { float t = v.z * obj; if (t > best) { best = t; bj = 1; } }
        { float t = v.w * obj; if (t > best) { best = t; bj = 2; } }
        #pragma unroll
        for (int j = 2; j <= 11; j++) {
            float4 u = rs[j];
            int c0 = 4 * j - 5;
            float t0 = u.x * obj; if (t0 > best) { best = t0; bj = c0; }
            float t1 = u.y * obj; if (t1 > best) { best = t1; bj = c0 + 1; }
            float t2 = u.z * obj; if (t2 > best) { best = t2; bj = c0 + 2; }
            float t3 = u.w * obj; if (t3 > best) { best = t3; bj = c0 + 3; }
        }
    } else {
        obj = s[row * STR + 4];
        // chunks 12..20: c = 4j-5..4j-2 (43..78) ; chunk 21: only .x (c79)
        #pragma unroll
        for (int j = 12; j <= 20; j++) {
            float4 u = rs[j];
            int c0 = 4 * j - 5;
            float t0 = u.x * obj; if (t0 > best) { best = t0; bj = c0; }
            float t1 = u.y * obj; if (t1 > best) { best = t1; bj = c0 + 1; }
            float t2 = u.z * obj; if (t2 > best) { best = t2; bj = c0 + 2; }
            float t3 = u.w * obj; if (t3 > best) { best = t3; bj = c0 + 3; }
        }
        { float t = rs[21].x * obj; if (t > best) { best = t; bj = 79; } }
    }

    // combine halves: odd wins only on strict > (tie -> even = lower class)
    float ob = __shfl_xor_sync(0xffffffffu, best, 1);
    int   oj = __shfl_xor_sync(0xffffffffu, bj, 1);
    if (half == 0 && ob > best) { best = ob; bj = oj; }

    bool valid = (half == 0) && (obj > CONF_T) && (best > CONF_T);

    int b = blockIdx.x / (NN / RPB);
    unsigned n = (unsigned)((blockIdx.x % (NN / RPB)) * RPB + row);
    u64 key = ((u64)__float_as_uint(best) << 32) | (u64)key_low(n, (unsigned)bj);

    unsigned m = __ballot_sync(0xffffffffu, valid);
    if (m) {
        int leader = __ffs(m) - 1;
        int base = 0;
        if (lane == leader) base = atomicAdd(&g_icnt[b], __popc(m));
        base = __shfl_sync(0xffffffffu, base, leader);
        if (valid) {
            int pos = base + __popc(m & ((1u << lane) - 1));
            if (pos < CAPI) g_cand[(size_t)b * CAPI + pos] = key;
        }
    }
}

// ---------------- 2) fused per-image: hist + threshold + bucket + NMS + out ----
// smem layout: [0,16K) hist (phase 1) overlaid by s_cls [0,40K) (phase 2+)
#define OFF_SORT  (NCLS * CAPC * 8)                       // 40960
#define OFF_CCNT  (OFF_SORT + 1024 * 8)                   // 49152
#define OFF_PART  (OFF_CCNT + NCLS * 4)                   // 49472
#define OFF_MISC  (OFF_PART + 256 * 4)                    // 50496
#define SMEM_POST (OFF_MISC + 32)

__global__ __launch_bounds__(256) void k_post(const float* __restrict__ pred,
                                              const float* __restrict__ logits,
                                              float* __restrict__ out) {
    extern __shared__ unsigned char dsm[];
    int* s_hist = (int*)dsm;                       // [4096] phase 1 only
    u64* s_cls  = (u64*)dsm;                       // [NCLS*CAPC] phase 2+
    u64* s_sort = (u64*)(dsm + OFF_SORT);          // [1024]
    int* s_ccnt = (int*)(dsm + OFF_CCNT);          // [NCLS]
    int* s_part = (int*)(dsm + OFF_PART);          // [256]
    int* s_misc = (int*)(dsm + OFF_MISC);          // [0]=T0bits [1]=kept

    int b = blockIdx.x;
    int tid = threadIdx.x;
    int w = tid >> 5, lane = tid & 31;

    int cnt = g_icnt[b]; if (cnt > CAPI) cnt = CAPI;

    // ---- phase 1: smem histogram of candidate score bits ----
    for (int i = tid; i < HBINS; i += 256) s_hist[i] = 0;
    __syncthreads();
    for (int i = tid; i < cnt; i += 256) {
        unsigned bits = (unsigned)(g_cand[(size_t)b * CAPI + i] >> 32);
        int bin = (int)((bits - HBASE) >> HSHIFT);
        if (bin < 0) bin = 0;
        if (bin > HBINS - 1) bin = HBINS - 1;
        atomicAdd(&s_hist[bin], 1);
    }
    __syncthreads();

    // ---- threshold: suffix scan ----
    {
        int sum = 0;
        #pragma unroll
        for (int i = 0; i < 16; i++) sum += s_hist[tid * 16 + i];
        s_part[tid] = sum;
        __syncthreads();
        for (int off = 1; off < 256; off <<= 1) {
            int add = (tid + off < 256) ? s_part[tid + off] : 0;
            __syncthreads();
            s_part[tid] += add;
            __syncthreads();
        }
        if (tid == 0) {
            unsigned bits;
            if (s_part[0] < SELECT_MIN) {
                bits = HBASE;
            } else {
                int ct = 255;
                while (s_part[ct] < SELECT_MIN) ct--;
                int cum = (ct < 255) ? s_part[ct + 1] : 0;
                int B = ct * 16;
                for (int bin = ct * 16 + 15; bin >= ct * 16; bin--) {
                    cum += s_hist[bin];
                    if (cum >= SELECT_MIN) { B = bin; break; }
                }
                bits = HBASE + ((unsigned)B << HSHIFT);
            }
            s_misc[0] = (int)bits;
        }
    }
    __syncthreads();
    u64 T = ((u64)(unsigned)s_misc[0]) << 32;

    // ---- phase 2 init (overlays hist) ----
    for (int i = tid; i < NCLS * CAPC; i += 256) s_cls[i] = 0ULL;
    for (int i = tid; i < 1024; i += 256) s_sort[i] = 0ULL;
    for (int i = tid; i < NCLS; i += 256) s_ccnt[i] = 0;
    if (tid == 0) s_misc[1] = 0;
    __syncthreads();

    // ---- filter candidates above T into per-class lists ----
    for (int i = tid; i < cnt; i += 256) {
        u64 key = g_cand[(size_t)b * CAPI + i];
        if (key >= T) {
            int c = (int)key_cls(key);
            int pos = atomicAdd(&s_ccnt[c], 1);
            if (pos < CAPC) s_cls[c * CAPC + pos] = key;
        }
    }
    __syncthreads();

    // ---- warp-per-class: sort + greedy NMS + compact kept ----
    for (int k10 = 0; k10 < NCLS / 8; k10++) {
        int c = w + 8 * k10;
        int cntc = s_ccnt[c]; if (cntc > CAPC) cntc = CAPC;
        if (cntc == 0) continue;
        u64* L = s_cls + c * CAPC;

        if (cntc > 1) {
            int m = 1; while (m < cntc) m <<= 1;
            for (int k = 2; k <= m; k <<= 1) {
                for (int j = k >> 1; j > 0; j >>= 1) {
                    for (int t = lane; t < m; t += 32) {
                        int p = t ^ j;
                        if (p > t) {
                            bool up = ((t & k) == 0);
                            u64 a = L[t], bb = L[p];
                            if ((a < bb) == up) { L[t] = bb; L[p] = a; }
                        }
                    }
                    __syncwarp();
                }
            }
        }

        float x0[2], y0[2], x1[2], y1[2], ar[2];
        unsigned supm = 0;
        float off = (float)c * MAXWH;
        #pragma unroll
        for (int s = 0; s < 2; s++) {
            int t = lane + 32 * s;
            if (t < cntc) {
                unsigned n = key_n(L[t]);
                const float* p = pred + ((size_t)b * NN + n) * 85;
                float cx = p[0], cy = p[1], wd = p[2], ht = p[3];
                float a0 = cx - wd * 0.5f, b0 = cy - ht * 0.5f;
                float a1 = cx + wd * 0.5f, b1 = cy + ht * 0.5f;
                a0 += off; b0 += off; a1 += off; b1 += off;
                x0[s] = a0; y0[s] = b0; x1[s] = a1; y1[s] = b1;
                ar[s] = (a1 - a0) * (b1 - b0);
            } else {
                supm |= 1u << s;
                x0[s] = 0; y0[s] = 0; x1[s] = 0; y1[s] = 0; ar[s] = 0;
            }
        }

        for (int i = 0; i < cntc; i++) {
            int src = i & 31, sl = i >> 5;
            float vx0 = sl ? x0[1] : x0[0];
            float vy0 = sl ? y0[1] : y0[0];
            float vx1 = sl ? x1[1] : x1[0];
            float vy1 = sl ? y1[1] : y1[0];
            float var = sl ? ar[1] : ar[0];
            unsigned ps = __shfl_sync(0xffffffffu, supm, src);
            float bx0 = __shfl_sync(0xffffffffu, vx0, src);
            float by0 = __shfl_sync(0xffffffffu, vy0, src);
            float bx1 = __shfl_sync(0xffffffffu, vx1, src);
            float by1 = __shfl_sync(0xffffffffu, vy1, src);
            float ba  = __shfl_sync(0xffffffffu, var, src);
            if ((ps >> sl) & 1) continue;
            #pragma unroll
            for (int s = 0; s < 2; s++) {
                int t = lane + 32 * s;
                if (t > i && !((supm >> s) & 1)) {
                    float ltx = fmaxf(bx0, x0[s]);
                    float lty = fmaxf(by0, y0[s]);
                    float rbx = fminf(bx1, x1[s]);
                    float rby = fminf(by1, y1[s]);
                    float iw = fmaxf(rbx - ltx, 0.0f);
                    float ih = fmaxf(rby - lty, 0.0f);
                    float inter = iw * ih;
                    float iou = inter / (((ba + ar[s]) - inter) + 1e-9f);
                    if (iou > IOU_T) supm |= 1u << s;
                }
            }
        }

        #pragma unroll
        for (int s = 0; s < 2; s++) {
            int t = lane + 32 * s;
            bool kp = (t < cntc) && !((supm >> s) & 1);
            unsigned mask = __ballot_sync(0xffffffffu, kp);
            if (mask) {
                int leader = __ffs(mask) - 1;
                int base = 0;
                if (lane == leader) base = atomicAdd(&s_misc[1], __popc(mask));
                base = __shfl_sync(0xffffffffu, base, leader);
                if (kp) {
                    int pos = base + __popc(mask & ((1u << lane) - 1));
                    if (pos < 1024) s_sort[pos] = L[t];
                }
            }
        }
    }
    __syncthreads();
    int kept = s_misc[1]; if (kept > 1024) kept = 1024;

    // ---- bitonic sort 1024 descending ----
    for (int k = 2; k <= 1024; k <<= 1) {
        for (int j = k >> 1; j > 0; j >>= 1) {
            for (int t = tid; t < 1024; t += 256) {
                int p = t ^ j;
                if (p > t) {
                    bool up = ((t & k) == 0);
                    u64 a = s_sort[t], bb = s_sort[p];
                    if ((a < bb) == up) { s_sort[t] = bb; s_sort[p] = a; }
                }
            }
            __syncthreads();
        }
    }

    int tsel = (kept < MAXDET) ? kept : MAXDET;

    float* dets  = out;                               // [16,300,6]
    float* lg    = out + (size_t)NB * MAXDET * 6;     // [16,300,80]
    float* keepo = out + (size_t)NB * MAXDET * 86;    // [16,300]

    for (int r = tid; r < MAXDET; r += 256) {
        float d0 = 0, d1 = 0, d2 = 0, d3 = 0, d4 = 0, d5 = 0, kf = 0;
        if (r < tsel) {
            u64 key = s_sort[r];
            unsigned n = key_n(key);
            float conf = __uint_as_float((unsigned)(key >> 32));
            const float* p = pred + ((size_t)b * NN + n) * 85;
            float cx = p[0], cy = p[1], wd = p[2], ht = p[3];
            d0 = cx - wd * 0.5f; d1 = cy - ht * 0.5f;
            d2 = cx + wd * 0.5f; d3 = cy + ht * 0.5f;
            d4 = conf; d5 = (float)key_cls(key); kf = 1.0f;
        }
        float* dr = dets + ((size_t)b * MAXDET + r) * 6;
        dr[0] = d0; dr[1] = d1; dr[2] = d2; dr[3] = d3; dr[4] = d4; dr[5] = d5;
        keepo[(size_t)b * MAXDET + r] = kf;
    }
    for (int idx = tid; idx < MAXDET * NCLS; idx += 256) {
        int r = idx / NCLS, col = idx % NCLS;
        float v = 0.0f;
        if (r < tsel)
            v = logits[((size_t)b * NN + key_n(s_sort[r])) * NCLS + col];
        lg[((size_t)b * MAXDET + r) * NCLS + col] = v;
    }
}

extern "C" void kernel_launch(void* const* d_in, const int* in_sizes, int n_in,
                              void* d_out, int out_size) {
    const float* pred;
    const float* logits;
    if (in_sizes[0] == NB * NN * 85) {
        pred = (const float*)d_in[0];
        logits = (const float*)d_in[1];
    } else {
        pred = (const float*)d_in[1];
        logits = (const float*)d_in[0];
    }
    float* out = (float*)d_out;

    cudaFuncSetAttribute(k_post, cudaFuncAttributeMaxDynamicSharedMemorySize,
                         SMEM_POST);

    k_init<<<1, 32>>>();
    k_decode<<<NB * (NN / RPB), 256>>>(pred);
    k_post<<<NB, 256, SMEM_POST>>>(pred, logits, out);
}

// round 14
// speedup vs baseline: 3.9545x; 1.1759x over previous
#include <cuda_runtime.h>
#include <cstdint>

#define NB     16
#define NN     25200
#define NCLS   80
#define MAXDET 300
#define CONF_T 0.25f
#define IOU_T  0.45f
#define MAXWH  4096.0f

#define HBINS   4096          // histogram bins over score bits
#define HBASE   0x3E800000u   // float bits of 0.25
#define HSHIFT  13
#define SELECT_MIN 600        // want >=600 candidates above threshold
#define CAPI   32768          // per-image candidate list capacity
#define CAPC   64             // per-(image,class) smem bucket capacity
#define CAPS   1024           // survivor list capacity

#define R_ITER   25           // rows per warp in decode
#define ROWS_PBK 200          // rows per decode block (8 warps * 25)
#define BLK_PI   126          // decode blocks per image (126*200 = 25200)

typedef unsigned long long u64;

// key = score_bits(32) | (0x7FFF - n)(15) | class(7)
__device__ __forceinline__ unsigned key_low(unsigned n, unsigned j) {
    return ((0x7FFFu - n) << 7) | j;
}
__device__ __forceinline__ unsigned key_n(u64 k) {
    return 0x7FFFu - (((unsigned)k >> 7) & 0x7FFFu);
}
__device__ __forceinline__ unsigned key_cls(u64 k) {
    return (unsigned)k & 0x7Fu;
}

// ---------------- scratch ----------------
__device__ int g_icnt[NB];
__device__ u64 g_cand[(size_t)NB * CAPI];

__global__ void k_init() {
    if (threadIdx.x < NB) g_icnt[threadIdx.x] = 0;
}

// ---------------- 1) decode: warp per row, fmax-only (no argmax) ------------
// conf = rnd(max_k(cls_k) * obj) == max_k rnd(cls_k*obj): rounding is monotone,
// obj >= 0 -> bit-exact vs reference. Class argmax deferred to k_post.
__global__ __launch_bounds__(256) void k_decode(const float* __restrict__ pred) {
    __shared__ u64 s_buf[ROWS_PBK];
    __shared__ int s_cnt;
    __shared__ int s_base;
    int tid = threadIdx.x, w = tid >> 5, lane = tid & 31;
    int b = blockIdx.x / BLK_PI;
    int n0 = (blockIdx.x % BLK_PI) * ROWS_PBK;

    if (tid == 0) s_cnt = 0;
    __syncthreads();

    for (int it = 0; it < R_ITER; it++) {
        int n = n0 + it * 8 + w;
        const float* p = pred + ((size_t)b * NN + n) * 85;
        float v0 = p[lane];                               // floats 0..31
        float v1 = p[32 + lane];                          // floats 32..63
        float v2 = (lane < 21) ? p[64 + lane] : -1.0f;    // floats 64..84
        float m = v1;                                     // always a class
        if (lane >= 5) m = fmaxf(m, v0);                  // skip box+obj
        m = fmaxf(m, v2);
        #pragma unroll
        for (int o = 16; o > 0; o >>= 1)
            m = fmaxf(m, __shfl_xor_sync(0xffffffffu, m, o));
        float obj = __shfl_sync(0xffffffffu, v0, 4);
        if (lane == 0) {
            float conf = m * obj;                         // bit-exact ref conf
            if (obj > CONF_T && conf > CONF_T) {
                int pos = atomicAdd(&s_cnt, 1);
                s_buf[pos] = ((u64)__float_as_uint(conf) << 32) |
                             (u64)key_low((unsigned)n, 0x7Fu);  // class later
            }
        }
    }
    __syncthreads();
    if (tid == 0) s_base = atomicAdd(&g_icnt[b], s_cnt);
    __syncthreads();
    for (int i = tid; i < s_cnt; i += 256) {
        int pos = s_base + i;
        if (pos < CAPI) g_cand[(size_t)b * CAPI + pos] = s_buf[i];
    }
}

// ---------------- 2) fused per-image post-processing (512 threads) ----------
// smem: [0,40K) hist(16K, phase1) overlaid by s_cls; then s_surv, s_sort, misc
#define OFF_SURV  (NCLS * CAPC * 8)                       // 40960
#define OFF_SORT  (OFF_SURV + CAPS * 8)                   // 49152
#define OFF_CCNT  (OFF_SORT + 1024 * 8)                   // 57344
#define OFF_PART  (OFF_CCNT + NCLS * 4)                   // 57664
#define OFF_MISC  (OFF_PART + 256 * 4)                    // 58688
#define SMEM_POST (OFF_MISC + 32)

__global__ __launch_bounds__(512) void k_post(const float* __restrict__ pred,
                                              const float* __restrict__ logits,
                                              float* __restrict__ out) {
    extern __shared__ unsigned char dsm[];
    int* s_hist = (int*)dsm;                       // [4096] phase 1 only
    u64* s_cls  = (u64*)dsm;                       // [NCLS*CAPC] phase 2+
    u64* s_surv = (u64*)(dsm + OFF_SURV);          // [CAPS]
    u64* s_sort = (u64*)(dsm + OFF_SORT);          // [1024]
    int* s_ccnt = (int*)(dsm + OFF_CCNT);          // [NCLS]
    int* s_part = (int*)(dsm + OFF_PART);          // [256]
    int* s_misc = (int*)(dsm + OFF_MISC);          // [0]=T0 [1]=kept [2]=scnt

    int b = blockIdx.x;
    int tid = threadIdx.x;
    int w = tid >> 5, lane = tid & 31;
    int NT = 512;

    int cnt = g_icnt[b]; if (cnt > CAPI) cnt = CAPI;

    // ---- phase 1: smem histogram of candidate score bits ----
    for (int i = tid; i < HBINS; i += NT) s_hist[i] = 0;
    if (tid == 0) s_misc[2] = 0;
    __syncthreads();
    for (int i = tid; i < cnt; i += NT) {
        unsigned bits = (unsigned)(g_cand[(size_t)b * CAPI + i] >> 32);
        int bin = (int)((bits - HBASE) >> HSHIFT);
        if (bin < 0) bin = 0;
        if (bin > HBINS - 1) bin = HBINS - 1;
        atomicAdd(&s_hist[bin], 1);
    }
    __syncthreads();

    // ---- threshold: suffix scan over 256 partials of 16 bins ----
    {
        int sum = 0;
        if (tid < 256) {
            #pragma unroll
            for (int i = 0; i < 16; i++) sum += s_hist[tid * 16 + i];
            s_part[tid] = sum;
        }
        __syncthreads();
        for (int off = 1; off < 256; off <<= 1) {
            int add = (tid < 256 && tid + off < 256) ? s_part[tid + off] : 0;
            __syncthreads();
            if (tid < 256) s_part[tid] += add;
            __syncthreads();
        }
        if (tid == 0) {
            unsigned bits;
            if (s_part[0] < SELECT_MIN) {
                bits = HBASE;
            } else {
                int ct = 255;
                while (s_part[ct] < SELECT_MIN) ct--;
                int cum = (ct < 255) ? s_part[ct + 1] : 0;
                int B = ct * 16;
                for (int bin = ct * 16 + 15; bin >= ct * 16; bin--) {
                    cum += s_hist[bin];
                    if (cum >= SELECT_MIN) { B = bin; break; }
                }
                bits = HBASE + ((unsigned)B << HSHIFT);
            }
            s_misc[0] = (int)bits;
        }
    }
    __syncthreads();
    u64 T = ((u64)(unsigned)s_misc[0]) << 32;

    // ---- compact survivors (>= T) into s_surv; independent loads ----
    for (int i = tid; i < cnt; i += NT) {
        u64 key = g_cand[(size_t)b * CAPI + i];
        if (key >= T) {
            int pos = atomicAdd(&s_misc[2], 1);
            if (pos < CAPS) s_surv[pos] = key;
        }
    }
    __syncthreads();
    int scnt = s_misc[2]; if (scnt > CAPS) scnt = CAPS;

    // ---- phase 2 init (overlays hist) ----
    for (int i = tid; i < NCLS * CAPC; i += NT) s_cls[i] = 0ULL;
    for (int i = tid; i < 1024; i += NT) s_sort[i] = 0ULL;
    for (int i = tid; i < NCLS; i += NT) s_ccnt[i] = 0;
    if (tid == 0) s_misc[1] = 0;
    __syncthreads();

    // ---- thread-per-survivor: exact ref argmax (product, first-max) + bucket -
    for (int i = tid; i < scnt; i += NT) {
        u64 key = s_surv[i];
        unsigned n = key_n(key);
        const float* p = pred + ((size_t)b * NN + n) * 85;
        float obj = p[4];
        float best = -1.0f; int bj = 0;
        #pragma unroll 8
        for (int k = 0; k < NCLS; k++) {
            float v = p[5 + k] * obj;               // exact reference arithmetic
            if (v > best) { best = v; bj = k; }     // strict > : first max
        }
        u64 nk = (key & ~0x7FULL) | (unsigned)bj;   // install real class
        int pos = atomicAdd(&s_ccnt[bj], 1);
        if (pos < CAPC) s_cls[bj * CAPC + pos] = nk;
    }
    __syncthreads();

    // ---- warp-per-class: sort + greedy NMS + compact kept (16 warps) ----
    for (int k5 = 0; k5 < NCLS / 16; k5++) {
        int c = w + 16 * k5;
        int cntc = s_ccnt[c]; if (cntc > CAPC) cntc = CAPC;
        if (cntc == 0) continue;
        u64* L = s_cls + c * CAPC;

        if (cntc > 1) {
            int m = 1; while (m < cntc) m <<= 1;
            for (int k = 2; k <= m; k <<= 1) {
                for (int j = k >> 1; j > 0; j >>= 1) {
                    for (int t = lane; t < m; t += 32) {
                        int p = t ^ j;
                        if (p > t) {
                            bool up = ((t & k) == 0);
                            u64 a = L[t], bb = L[p];
                            if ((a < bb) == up) { L[t] = bb; L[p] = a; }
                        }
                    }
                    __syncwarp();
                }
            }
        }

        float x0[2], y0[2], x1[2], y1[2], ar[2];
        unsigned supm = 0;
        float off = (float)c * MAXWH;
        #pragma unroll
        for (int s = 0; s < 2; s++) {
            int t = lane + 32 * s;
            if (t < cntc) {
                unsigned n = key_n(L[t]);
                const float* p = pred + ((size_t)b * NN + n) * 85;
                float cx = p[0], cy = p[1], wd = p[2], ht = p[3];
                float a0 = cx - wd * 0.5f, b0 = cy - ht * 0.5f;
                float a1 = cx + wd * 0.5f, b1 = cy + ht * 0.5f;
                a0 += off; b0 += off; a1 += off; b1 += off;
                x0[s] = a0; y0[s] = b0; x1[s] = a1; y1[s] = b1;
                ar[s] = (a1 - a0) * (b1 - b0);
            } else {
                supm |= 1u << s;
                x0[s] = 0; y0[s] = 0; x1[s] = 0; y1[s] = 0; ar[s] = 0;
            }
        }

        for (int i = 0; i < cntc; i++) {
            int src = i & 31, sl = i >> 5;
            float vx0 = sl ? x0[1] : x0[0];
            float vy0 = sl ? y0[1] : y0[0];
            float vx1 = sl ? x1[1] : x1[0];
            float vy1 = sl ? y1[1] : y1[0];
            float var = sl ? ar[1] : ar[0];
            unsigned ps = __shfl_sync(0xffffffffu, supm, src);
            float bx0 = __shfl_sync(0xffffffffu, vx0, src);
            float by0 = __shfl_sync(0xffffffffu, vy0, src);
            float bx1 = __shfl_sync(0xffffffffu, vx1, src);
            float by1 = __shfl_sync(0xffffffffu, vy1, src);
            float ba  = __shfl_sync(0xffffffffu, var, src);
            if ((ps >> sl) & 1) continue;
            #pragma unroll
            for (int s = 0; s < 2; s++) {
                int t = lane + 32 * s;
                if (t > i && !((supm >> s) & 1)) {
                    float ltx = fmaxf(bx0, x0[s]);
                    float lty = fmaxf(by0, y0[s]);
                    float rbx = fminf(bx1, x1[s]);
                    float rby = fminf(by1, y1[s]);
                    float iw = fmaxf(rbx - ltx, 0.0f);
                    float ih = fmaxf(rby - lty, 0.0f);
                    float inter = iw * ih;
                    float iou = inter / (((ba + ar[s]) - inter) + 1e-9f);
                    if (iou > IOU_T) supm |= 1u << s;
                }
            }
        }

        #pragma unroll
        for (int s = 0; s < 2; s++) {
            int t = lane + 32 * s;
            bool kp = (t < cntc) && !((supm >> s) & 1);
            unsigned mask = __ballot_sync(0xffffffffu, kp);
            if (mask) {
                int leader = __ffs(mask) - 1;
                int base = 0;
                if (lane == leader) base = atomicAdd(&s_misc[1], __popc(mask));
                base = __shfl_sync(0xffffffffu, base, leader);
                if (kp) {
                    int pos = base + __popc(mask & ((1u << lane) - 1));
                    if (pos < 1024) s_sort[pos] = L[t];
                }
            }
        }
    }
    __syncthreads();
    int kept = s_misc[1]; if (kept > 1024) kept = 1024;

    // ---- bitonic sort 1024 descending (512 threads: 1 elem pair each) ----
    for (int k = 2; k <= 1024; k <<= 1) {
        for (int j = k >> 1; j > 0; j >>= 1) {
            for (int t = tid; t < 1024; t += NT) {
                int p = t ^ j;
                if (p > t) {
                    bool up = ((t & k) == 0);
                    u64 a = s_sort[t], bb = s_sort[p];
                    if ((a < bb) == up) { s_sort[t] = bb; s_sort[p] = a; }
                }
            }
            __syncthreads();
        }
    }

    int tsel = (kept < MAXDET) ? kept : MAXDET;

    float* dets  = out;                               // [16,300,6]
    float* lg    = out + (size_t)NB * MAXDET * 6;     // [16,300,80]
    float* keepo = out + (size_t)NB * MAXDET * 86;    // [16,300]

    for (int r = tid; r < MAXDET; r += NT) {
        float d0 = 0, d1 = 0, d2 = 0, d3 = 0, d4 = 0, d5 = 0, kf = 0;
        if (r < tsel) {
            u64 key = s_sort[r];
            unsigned n = key_n(key);
            float conf = __uint_as_float((unsigned)(key >> 32));
            const float* p = pred + ((size_t)b * NN + n) * 85;
            float cx = p[0], cy = p[1], wd = p[2], ht = p[3];
            d0 = cx - wd * 0.5f; d1 = cy - ht * 0.5f;
            d2 = cx + wd * 0.5f; d3 = cy + ht * 0.5f;
            d4 = conf; d5 = (float)key_cls(key); kf = 1.0f;
        }
        float* dr = dets + ((size_t)b * MAXDET + r) * 6;
        dr[0] = d0; dr[1] = d1; dr[2] = d2; dr[3] = d3; dr[4] = d4; dr[5] = d5;
        keepo[(size_t)b * MAXDET + r] = kf;
    }
    for (int idx = tid; idx < MAXDET * NCLS; idx += NT) {
        int r = idx / NCLS, col = idx % NCLS;
        float v = 0.0f;
        if (r < tsel)
            v = logits[((size_t)b * NN + key_n(s_sort[r])) * NCLS + col];
        lg[((size_t)b * MAXDET + r) * NCLS + col] = v;
    }
}

extern "C" void kernel_launch(void* const* d_in, const int* in_sizes, int n_in,
                              void* d_out, int out_size) {
    const float* pred;
    const float* logits;
    if (in_sizes[0] == NB * NN * 85) {
        pred = (const float*)d_in[0];
        logits = (const float*)d_in[1];
    } else {
        pred = (const float*)d_in[1];
        logits = (const float*)d_in[0];
    }
    float* out = (float*)d_out;

    cudaFuncSetAttribute(k_post, cudaFuncAttributeMaxDynamicSharedMemorySize,
                         SMEM_POST);

    k_init<<<1, 32>>>();
    k_decode<<<NB * BLK_PI, 256>>>(pred);
    k_post<<<NB, 512, SMEM_POST>>>(pred, logits, out);
}